// round 8
// baseline (speedup 1.0000x reference)
#include <cuda_runtime.h>
#include <cuda_bf16.h>
#include <cstdint>

typedef uint32_t u32;
typedef uint64_t u64;
typedef unsigned short u16;

// ---------------------------------------------------------------------------
// MLSTMFixD round 8:
//  - bf16 3-term split GEMMs (fp32-accurate) via mma.sync (sm_103-safe)
//  - XW = x@Wmih^T hoisted (one big GEMM, streaming stores/loads)
//  - gate-grouped weight permutation -> epilogues FUSED into the step GEMMs
//  - 2 kernels per timestep, no G round trips, hist kept L2-resident
// ---------------------------------------------------------------------------

constexpr int T_   = 128;
constexpr int B_   = 256;
constexpr int I_   = 512;
constexpr int H_   = 512;
constexpr int O_   = 5;
constexpr int KLAG = 32;
constexpr int BH   = B_ * H_;
constexpr int N1   = 3 * H_;   // 1536
constexpr int N2   = 4 * H_;   // 2048

constexpr int SMEM_X  = 2 * 32768;   // XW gemm: 2 stages x 32KB
constexpr int SMEM_S1 = 2 * 32768;   // step1:   2 stages x 32KB (A 8K, B 24K)
constexpr int SMEM_S2 = 2 * 40960;   // step2:   2 stages x 40KB (A 8K, B 32K)

// ------------------------- device scratch (static) -------------------------
__device__ __align__(16) u16 g_xhi[T_ * B_ * I_], g_xlo[T_ * B_ * I_];
__device__ __align__(16) u16 g_WxHi[N1 * 512],  g_WxLo[N1 * 512];      // Wmih plain
__device__ __align__(16) u16 g_W1pHi[16 * 96 * 512],  g_W1pLo[16 * 96 * 512];   // Wmhh gate-grouped
__device__ __align__(16) u16 g_W2pHi[16 * 128 * 1024], g_W2pLo[16 * 128 * 1024]; // [Wih|Whh] gate-grouped
__device__ __align__(16) u16 g_h1hi[BH], g_h1lo[BH];
__device__ __align__(16) u16 g_h2hi[BH], g_h2lo[BH];
__device__ float g_c2[BH];
__device__ float g_sel[BH];
__device__ float g_hist[KLAG][BH];          // circular by (t & 31)
__device__ float g_wd[KLAG][H_];
__device__ float g_bs1[N1];                 // bmih + bmhh
__device__ float g_bs2[N2];                 // bih + bhh
__device__ float g_XW[(size_t)T_ * B_ * N1];  // x @ Wmih^T for all t (streamed)

// ------------------------------- helpers ------------------------------------
__device__ __forceinline__ u32 smem_u32(const void* p) {
    u32 a;
    asm("{ .reg .u64 t; cvta.to.shared.u64 t, %1; cvt.u32.u64 %0, t; }" : "=r"(a) : "l"(p));
    return a;
}
__device__ __forceinline__ void cpasync16(u32 dst, const void* src) {
    asm volatile("cp.async.cg.shared.global [%0], [%1], 16;" :: "r"(dst), "l"(src));
}
#define CP_COMMIT() asm volatile("cp.async.commit_group;" ::: "memory")
#define CP_WAIT0()  asm volatile("cp.async.wait_group 0;" ::: "memory")

#define LDSM4(r, addr) asm volatile(                                           \
    "ldmatrix.sync.aligned.m8n8.x4.shared.b16 {%0,%1,%2,%3}, [%4];"            \
    : "=r"((r)[0]), "=r"((r)[1]), "=r"((r)[2]), "=r"((r)[3]) : "r"(addr))

#define MMA(d, a, b0, b1) asm volatile(                                        \
    "mma.sync.aligned.m16n8k16.row.col.f32.bf16.bf16.f32 "                     \
    "{%0,%1,%2,%3}, {%4,%5,%6,%7}, {%8,%9}, {%0,%1,%2,%3};"                    \
    : "+f"((d)[0]), "+f"((d)[1]), "+f"((d)[2]), "+f"((d)[3])                   \
    : "r"((a)[0]), "r"((a)[1]), "r"((a)[2]), "r"((a)[3]), "r"(b0), "r"(b1))

__device__ __forceinline__ u16 bf16bits(__nv_bfloat16 v) {
    __nv_bfloat16_raw r = *reinterpret_cast<__nv_bfloat16_raw*>(&v);
    return r.x;
}
__device__ __forceinline__ void split1(float a, u16& h, u16& l) {
    __nv_bfloat16 bh = __float2bfloat16_rn(a);
    float r = a - __bfloat162float(bh);
    __nv_bfloat16 bl = __float2bfloat16_rn(r);
    h = bf16bits(bh);
    l = bf16bits(bl);
}
__device__ __forceinline__ void split4(float4 v, u32& h01, u32& h23, u32& l01, u32& l23) {
    u16 h0, l0, h1, l1, h2, l2, h3, l3;
    split1(v.x, h0, l0); split1(v.y, h1, l1);
    split1(v.z, h2, l2); split1(v.w, h3, l3);
    h01 = (u32)h0 | ((u32)h1 << 16);  h23 = (u32)h2 | ((u32)h3 << 16);
    l01 = (u32)l0 | ((u32)l1 << 16);  l23 = (u32)l2 | ((u32)l3 << 16);
}
__device__ __forceinline__ float sigf(float x) { return 1.0f / (1.0f + expf(-x)); }

// ------------------------------- init ---------------------------------------
__global__ __launch_bounds__(256) void init_kernel(
    const float* __restrict__ b_d,  const float* __restrict__ x,
    const float* __restrict__ Wmih, const float* __restrict__ Wmhh,
    const float* __restrict__ Wih,  const float* __restrict__ Whh,
    const float* __restrict__ bmih, const float* __restrict__ bmhh,
    const float* __restrict__ bih,  const float* __restrict__ bhh)
{
    const int tid = blockIdx.x * blockDim.x + threadIdx.x;
    const int tot = gridDim.x * blockDim.x;

    // x split
    const int ngx = T_ * B_ * I_ / 4;
    for (int i = tid; i < ngx; i += tot) {
        float4 v = reinterpret_cast<const float4*>(x)[i];
        u32 h01, h23, l01, l23; split4(v, h01, h23, l01, l23);
        reinterpret_cast<uint2*>(g_xhi)[i] = make_uint2(h01, h23);
        reinterpret_cast<uint2*>(g_xlo)[i] = make_uint2(l01, l23);
    }

    // Wmih plain split
    const int ngWx = N1 * 512 / 4;
    for (int i = tid; i < ngWx; i += tot) {
        float4 v = reinterpret_cast<const float4*>(Wmih)[i];
        u32 h01, h23, l01, l23; split4(v, h01, h23, l01, l23);
        reinterpret_cast<uint2*>(g_WxHi)[i] = make_uint2(h01, h23);
        reinterpret_cast<uint2*>(g_WxLo)[i] = make_uint2(l01, l23);
    }

    // Wmhh gate-grouped: panel ht (0..15), row r = gate*32+c  <- orig n = gate*512 + ht*32 + c
    const int ngW1 = 16 * 96 * 512 / 4;
    for (int i = tid; i < ngW1; i += tot) {
        int e = i * 4;
        int ht = e / (96 * 512);
        int rem = e - ht * (96 * 512);
        int r = rem >> 9, k = rem & 511;
        int gate = r >> 5, c = r & 31;
        int n = gate * 512 + ht * 32 + c;
        float4 v = *reinterpret_cast<const float4*>(Wmhh + (size_t)n * 512 + k);
        u32 h01, h23, l01, l23; split4(v, h01, h23, l01, l23);
        reinterpret_cast<uint2*>(g_W1pHi)[i] = make_uint2(h01, h23);
        reinterpret_cast<uint2*>(g_W1pLo)[i] = make_uint2(l01, l23);
    }

    // [Wih|Whh] gate-grouped: panel ht, row r = gate*32+c, k 0..1023
    const int ngW2 = 16 * 128 * 1024 / 4;
    for (int i = tid; i < ngW2; i += tot) {
        int e = i * 4;
        int ht = e >> 17;
        int rem = e & 131071;
        int r = rem >> 10, k = rem & 1023;
        int gate = r >> 5, c = r & 31;
        int n = gate * 512 + ht * 32 + c;
        const float* src = (k < 512) ? (Wih + (size_t)n * 512 + k)
                                     : (Whh + (size_t)n * 512 + (k - 512));
        float4 v = *reinterpret_cast<const float4*>(src);
        u32 h01, h23, l01, l23; split4(v, h01, h23, l01, l23);
        reinterpret_cast<uint2*>(g_W2pHi)[i] = make_uint2(h01, h23);
        reinterpret_cast<uint2*>(g_W2pLo)[i] = make_uint2(l01, l23);
    }

    // bias sums
    for (int i = tid; i < N1; i += tot) g_bs1[i] = bmih[i] + bmhh[i];
    for (int i = tid; i < N2; i += tot) g_bs2[i] = bih[i] + bhh[i];

    // zero state
    float4 z4 = make_float4(0.f, 0.f, 0.f, 0.f);
    for (int i = tid; i < KLAG * BH / 4; i += tot)
        reinterpret_cast<float4*>(&g_hist[0][0])[i] = z4;
    for (int i = tid; i < BH / 4; i += tot) {
        reinterpret_cast<float4*>(g_c2)[i]  = z4;
        reinterpret_cast<float4*>(g_sel)[i] = z4;
        reinterpret_cast<uint2*>(g_h1hi)[i] = make_uint2(0u, 0u);
        reinterpret_cast<uint2*>(g_h1lo)[i] = make_uint2(0u, 0u);
        reinterpret_cast<uint2*>(g_h2hi)[i] = make_uint2(0u, 0u);
        reinterpret_cast<uint2*>(g_h2lo)[i] = make_uint2(0u, 0u);
    }

    // frac-diff coefficients
    if (tid < H_) {
        float d = 0.5f * (1.0f / (1.0f + expf(-b_d[tid])));
        float c = 1.0f;
        for (int j = 1; j <= KLAG; j++) {
            c *= ((float)(j - 1) - d) / (float)j;
            g_wd[j - 1][tid] = c;
        }
    }
}

// ------------------- XW precompute: XW = x @ Wmih^T --------------------------
// CTA 64x64, 8 warps (warp 32x16), K=512 in 8 chunks, 2-stage, streaming stores.
__global__ __launch_bounds__(256, 2) void gemmx_kernel()
{
    extern __shared__ __align__(128) char smem[];
    const u32 sb  = smem_u32(smem);
    const int tid = threadIdx.x;
    const int wid = tid >> 5, lane = tid & 31;
    const int bn  = blockIdx.x * 64;
    const int bm  = blockIdx.y * 64;

    const int lr  = tid >> 3;          // 0..31
    const int lcu = tid & 7;
    auto load_chunk = [&](int c, int stage) {
        const int k0 = c * 64;
        const u32 base = sb + stage * 32768;
#pragma unroll
        for (int j = 0; j < 2; j++) {
            const int r = lr + j * 32;
            const u32 so = (u32)(r * 128 + ((lcu ^ (r & 7)) << 4));
            const size_t ao = (size_t)(bm + r) * 512 + k0 + lcu * 8;
            const size_t bo = (size_t)(bn + r) * 512 + k0 + lcu * 8;
            cpasync16(base + so,         g_xhi  + ao);
            cpasync16(base + 8192 + so,  g_xlo  + ao);
            cpasync16(base + 16384 + so, g_WxHi + bo);
            cpasync16(base + 24576 + so, g_WxLo + bo);
        }
    };

    const int warp_m = wid & 1;
    const int warp_n = wid >> 1;
    const int arow   = warp_m * 32 + (lane & 15);
    const int akh    = lane >> 4;
    const int asw    = arow & 7;
    const u32 aoff0  = (u32)(arow * 128);
    const u32 aoff1  = (u32)((arow + 16) * 128);
    const int brow   = warp_n * 16 + (lane & 7) + ((lane >> 4) << 3);
    const int bkh    = (lane >> 3) & 1;
    const int bsw    = brow & 7;
    const u32 boff   = (u32)(brow * 128);

    float acc[2][2][4] = {};

    load_chunk(0, 0); CP_COMMIT();
    for (int c = 0; c < 8; c++) {
        CP_WAIT0();
        __syncthreads();
        if (c + 1 < 8) { load_chunk(c + 1, (c + 1) & 1); CP_COMMIT(); }

        const u32 Ah = sb + (c & 1) * 32768;
        const u32 Al = Ah + 8192;
        const u32 Bh = Ah + 16384;
        const u32 Bl = Ah + 24576;
#pragma unroll
        for (int kk = 0; kk < 4; kk++) {
            const u32 sa  = (((u32)(kk * 2 + akh) ^ (u32)asw) << 4);
            const u32 sbo = (((u32)(kk * 2 + bkh) ^ (u32)bsw) << 4);
            u32 ah0[4], ah1[4], al0[4], al1[4], bh[4], bl[4];
            LDSM4(ah0, Ah + aoff0 + sa);
            LDSM4(ah1, Ah + aoff1 + sa);
            LDSM4(al0, Al + aoff0 + sa);
            LDSM4(al1, Al + aoff1 + sa);
            LDSM4(bh,  Bh + boff + sbo);
            LDSM4(bl,  Bl + boff + sbo);
#pragma unroll
            for (int nt = 0; nt < 2; nt++) {
                MMA(acc[0][nt], ah0, bh[2 * nt], bh[2 * nt + 1]);
                MMA(acc[1][nt], ah1, bh[2 * nt], bh[2 * nt + 1]);
                MMA(acc[0][nt], ah0, bl[2 * nt], bl[2 * nt + 1]);
                MMA(acc[1][nt], ah1, bl[2 * nt], bl[2 * nt + 1]);
                MMA(acc[0][nt], al0, bh[2 * nt], bh[2 * nt + 1]);
                MMA(acc[1][nt], al1, bh[2 * nt], bh[2 * nt + 1]);
            }
        }
    }

#pragma unroll
    for (int mt = 0; mt < 2; mt++)
#pragma unroll
        for (int nt = 0; nt < 2; nt++) {
            const int gm = bm + warp_m * 32 + mt * 16 + (lane >> 2);
            const int gn = bn + warp_n * 16 + nt * 8 + 2 * (lane & 3);
            __stcs(reinterpret_cast<float2*>(&g_XW[(size_t)gm * N1 + gn]),
                   make_float2(acc[mt][nt][0], acc[mt][nt][1]));
            __stcs(reinterpret_cast<float2*>(&g_XW[(size_t)(gm + 8) * N1 + gn]),
                   make_float2(acc[mt][nt][2], acc[mt][nt][3]));
        }
}

// ------------------- step1: h1 @ Wmhh^T + fused mLSTM epilogue ---------------
// CTA 32m x 96n (32 hc x 3 gates), 384 thr (12 warps 2m x 6n, warp 16x16),
// K=512 in 8 chunks, 2-stage. Epilogue: gates -> frac filter -> hist + h1n.
__global__ __launch_bounds__(384, 1) void step1_kernel(int t)
{
    extern __shared__ __align__(128) char smem[];
    const u32 sb  = smem_u32(smem);
    const int tid = threadIdx.x;
    const int wid = tid >> 5, lane = tid & 31;
    const int ht  = blockIdx.x;          // hc tile
    const int bm  = blockIdx.y * 32;     // batch rows
    const int wm  = wid & 1;
    const int wn  = wid >> 1;            // 0..5

    const int arow = wm * 16 + (lane & 15);
    const int akh  = lane >> 4;
    const int asw  = arow & 7;
    const u32 aoff = (u32)(arow * 128);
    const int brow = wn * 16 + (lane & 7) + ((lane >> 4) << 3);
    const int bkh  = (lane >> 3) & 1;
    const int bsw  = brow & 7;
    const u32 boff = (u32)(brow * 128);

    auto load_chunk = [&](int c, int stage) {
        const int k0 = c * 64;
        const u32 base = sb + stage * 32768;
#pragma unroll
        for (int u = 0; u < 6; u++) {
            int idx = tid + u * 384;
            if (idx < 512) {             // A hi/lo (256 units each)
                int half = idx >> 8;
                int j = idx & 255;
                int r = j >> 3, cu = j & 7;
                const u16* src = (half ? g_h1lo : g_h1hi) + (size_t)(bm + r) * 512 + k0 + cu * 8;
                cpasync16(base + half * 4096 + (u32)(r * 128 + ((cu ^ (r & 7)) << 4)), src);
            } else if (idx < 2048) {     // B hi/lo (768 units each)
                int j = idx - 512;
                int half = (j >= 768); j -= half * 768;
                int r = j >> 3, cu = j & 7;
                const u16* src = (half ? g_W1pLo : g_W1pHi)
                               + ((size_t)ht * 96 + r) * 512 + k0 + cu * 8;
                cpasync16(base + 8192 + half * 12288 + (u32)(r * 128 + ((cu ^ (r & 7)) << 4)), src);
            }
        }
    };

    float acc[2][4] = {};

    load_chunk(0, 0); CP_COMMIT();
    for (int c = 0; c < 8; c++) {
        CP_WAIT0();
        __syncthreads();
        if (c + 1 < 8) { load_chunk(c + 1, (c + 1) & 1); CP_COMMIT(); }

        const u32 Ah = sb + (c & 1) * 32768;
        const u32 Al = Ah + 4096;
        const u32 Bh = Ah + 8192;
        const u32 Bl = Ah + 20480;
#pragma unroll
        for (int kk = 0; kk < 4; kk++) {
            const u32 sa  = (((u32)(kk * 2 + akh) ^ (u32)asw) << 4);
            const u32 sbo = (((u32)(kk * 2 + bkh) ^ (u32)bsw) << 4);
            u32 ah[4], al[4], bh[4], bl[4];
            LDSM4(ah, Ah + aoff + sa);
            LDSM4(al, Al + aoff + sa);
            LDSM4(bh, Bh + boff + sbo);
            LDSM4(bl, Bl + boff + sbo);
#pragma unroll
            for (int nt = 0; nt < 2; nt++) {
                MMA(acc[nt], ah, bh[2 * nt], bh[2 * nt + 1]);
                MMA(acc[nt], ah, bl[2 * nt], bl[2 * nt + 1]);
                MMA(acc[nt], al, bh[2 * nt], bh[2 * nt + 1]);
            }
        }
    }

    // stage accumulators: [32 rows][96+4 pad]
    float* stg = reinterpret_cast<float*>(smem);
    const int r0 = wm * 16 + (lane >> 2);
#pragma unroll
    for (int nt = 0; nt < 2; nt++) {
        int cn = wn * 16 + nt * 8 + 2 * (lane & 3);
        stg[r0 * 100 + cn]           = acc[nt][0];
        stg[r0 * 100 + cn + 1]       = acc[nt][1];
        stg[(r0 + 8) * 100 + cn]     = acc[nt][2];
        stg[(r0 + 8) * 100 + cn + 1] = acc[nt][3];
    }
    __syncthreads();

    // fused mLSTM epilogue
    for (int p = tid; p < 1024; p += 384) {
        const int row = p >> 5, hcl = p & 31;
        const int b = bm + row, hc = ht * 32 + hcl;
        const int idx = b * 512 + hc;
        const float* __restrict__ xw = g_XW + ((size_t)t * B_ + b) * N1;

        float gi = stg[row * 100 + hcl]      + __ldcs(xw + hc)         + g_bs1[hc];
        float go = stg[row * 100 + 32 + hcl] + __ldcs(xw + 512 + hc)   + g_bs1[512 + hc];
        float gg = stg[row * 100 + 64 + hcl] + __ldcs(xw + 1024 + hc)  + g_bs1[1024 + hc];
        float vi = sigf(gi), vo = sigf(go), vg = tanhf(gg);

        float fs = 0.0f;
#pragma unroll
        for (int j = 1; j <= KLAG; j++)
            fs = fmaf(g_wd[j - 1][hc], g_hist[(t - j) & (KLAG - 1)][idx], fs);

        float c1 = vi * vg - fs;
        g_hist[t & (KLAG - 1)][idx] = c1;
        split1(vo * tanhf(c1), g_h1hi[idx], g_h1lo[idx]);
    }
}

// ------------------- step2: [h1n|h2] @ W2^T + fused LSTM epilogue ------------
// CTA 32m x 128n (32 hc x 4 gates), 512 thr (16 warps 2m x 8n, warp 16x16),
// K=1024 in 16 chunks, 2-stage.
__global__ __launch_bounds__(512, 1) void step2_kernel(const int* __restrict__ length, int t)
{
    extern __shared__ __align__(128) char smem[];
    const u32 sb  = smem_u32(smem);
    const int tid = threadIdx.x;
    const int wid = tid >> 5, lane = tid & 31;
    const int ht  = blockIdx.x;
    const int bm  = blockIdx.y * 32;
    const int wm  = wid & 1;
    const int wn  = wid >> 1;            // 0..7

    const int arow = wm * 16 + (lane & 15);
    const int akh  = lane >> 4;
    const int asw  = arow & 7;
    const u32 aoff = (u32)(arow * 128);
    const int brow = wn * 16 + (lane & 7) + ((lane >> 4) << 3);
    const int bkh  = (lane >> 3) & 1;
    const int bsw  = brow & 7;
    const u32 boff = (u32)(brow * 128);

    auto load_chunk = [&](int c, int stage) {
        const int k0 = c * 64;
        const u32 base = sb + stage * 40960;
#pragma unroll
        for (int u = 0; u < 5; u++) {
            int idx = tid + u * 512;     // 0..2559
            if (idx < 512) {             // A hi/lo
                int half = idx >> 8;
                int j = idx & 255;
                int r = j >> 3, cu = j & 7;
                const u16* src;
                if (k0 < 512) src = (half ? g_h1lo : g_h1hi) + (size_t)(bm + r) * 512 + k0 + cu * 8;
                else          src = (half ? g_h2lo : g_h2hi) + (size_t)(bm + r) * 512 + (k0 - 512) + cu * 8;
                cpasync16(base + half * 4096 + (u32)(r * 128 + ((cu ^ (r & 7)) << 4)), src);
            } else {                     // B hi/lo (1024 units each)
                int j = idx - 512;
                int half = j >> 10; j &= 1023;
                int r = j >> 3, cu = j & 7;
                const u16* src = (half ? g_W2pLo : g_W2pHi)
                               + ((size_t)ht * 128 + r) * 1024 + k0 + cu * 8;
                cpasync16(base + 8192 + half * 16384 + (u32)(r * 128 + ((cu ^ (r & 7)) << 4)), src);
            }
        }
    };

    float acc[2][4] = {};

    load_chunk(0, 0); CP_COMMIT();
    for (int c = 0; c < 16; c++) {
        CP_WAIT0();
        __syncthreads();
        if (c + 1 < 16) { load_chunk(c + 1, (c + 1) & 1); CP_COMMIT(); }

        const u32 Ah = sb + (c & 1) * 40960;
        const u32 Al = Ah + 4096;
        const u32 Bh = Ah + 8192;
        const u32 Bl = Ah + 24576;
#pragma unroll
        for (int kk = 0; kk < 4; kk++) {
            const u32 sa  = (((u32)(kk * 2 + akh) ^ (u32)asw) << 4);
            const u32 sbo = (((u32)(kk * 2 + bkh) ^ (u32)bsw) << 4);
            u32 ah[4], al[4], bh[4], bl[4];
            LDSM4(ah, Ah + aoff + sa);
            LDSM4(al, Al + aoff + sa);
            LDSM4(bh, Bh + boff + sbo);
            LDSM4(bl, Bl + boff + sbo);
#pragma unroll
            for (int nt = 0; nt < 2; nt++) {
                MMA(acc[nt], ah, bh[2 * nt], bh[2 * nt + 1]);
                MMA(acc[nt], ah, bl[2 * nt], bl[2 * nt + 1]);
                MMA(acc[nt], al, bh[2 * nt], bh[2 * nt + 1]);
            }
        }
    }

    // stage accumulators: [32 rows][128+4 pad]
    float* stg = reinterpret_cast<float*>(smem);
    const int r0 = wm * 16 + (lane >> 2);
#pragma unroll
    for (int nt = 0; nt < 2; nt++) {
        int cn = wn * 16 + nt * 8 + 2 * (lane & 3);
        stg[r0 * 132 + cn]           = acc[nt][0];
        stg[r0 * 132 + cn + 1]       = acc[nt][1];
        stg[(r0 + 8) * 132 + cn]     = acc[nt][2];
        stg[(r0 + 8) * 132 + cn + 1] = acc[nt][3];
    }
    __syncthreads();

    // fused LSTM epilogue
    for (int p = tid; p < 1024; p += 512) {
        const int row = p >> 5, hcl = p & 31;
        const int b = bm + row, hc = ht * 32 + hcl;
        const int idx = b * 512 + hc;

        float xi = sigf (stg[row * 132 + hcl]       + g_bs2[hc]);
        float xf = sigf (stg[row * 132 + 32 + hcl]  + g_bs2[512 + hc]);
        float xg = tanhf(stg[row * 132 + 64 + hcl]  + g_bs2[1024 + hc]);
        float xo = sigf (stg[row * 132 + 96 + hcl]  + g_bs2[1536 + hc]);

        float cn = xf * g_c2[idx] + xi * xg;
        g_c2[idx] = cn;
        float hv = tanhf(xo * tanhf(cn));
        split1(hv, g_h2hi[idx], g_h2lo[idx]);
        if (length[b] == t) g_sel[idx] = hv;
    }
}

// ------------------------------- head ---------------------------------------
__global__ __launch_bounds__(128) void head_kernel(
    const float* __restrict__ Wout, const float* __restrict__ bout,
    float* __restrict__ out)
{
    const int warp = (blockIdx.x * blockDim.x + threadIdx.x) >> 5;
    const int lane = threadIdx.x & 31;
    if (warp >= B_) return;

    float p[O_] = {0.f, 0.f, 0.f, 0.f, 0.f};
    for (int h = lane; h < H_; h += 32) {
        float s = g_sel[warp * H_ + h];
#pragma unroll
        for (int o = 0; o < O_; o++) p[o] = fmaf(s, Wout[o * H_ + h], p[o]);
    }
#pragma unroll
    for (int o = 0; o < O_; o++)
#pragma unroll
        for (int off = 16; off > 0; off >>= 1)
            p[o] += __shfl_xor_sync(0xffffffffu, p[o], off);

    if (lane == 0) {
        float l[O_], m = -1e30f;
#pragma unroll
        for (int o = 0; o < O_; o++) { l[o] = p[o] + bout[o]; m = fmaxf(m, l[o]); }
        float s = 0.0f;
#pragma unroll
        for (int o = 0; o < O_; o++) s += expf(l[o] - m);
        float ls = logf(s);
#pragma unroll
        for (int o = 0; o < O_; o++) out[warp * O_ + o] = l[o] - m - ls;
    }
}

// ----------------------------- launcher -------------------------------------
extern "C" void kernel_launch(void* const* d_in, const int* in_sizes, int n_in,
                              void* d_out, int out_size)
{
    const float* x    = (const float*)d_in[0];
    const int*   len  = (const int*)  d_in[1];
    const float* b_d  = (const float*)d_in[2];
    const float* Wmih = (const float*)d_in[3];
    const float* Wmhh = (const float*)d_in[4];
    const float* bmih = (const float*)d_in[5];
    const float* bmhh = (const float*)d_in[6];
    const float* Wih  = (const float*)d_in[7];
    const float* Whh  = (const float*)d_in[8];
    const float* bih  = (const float*)d_in[9];
    const float* bhh  = (const float*)d_in[10];
    const float* Wout = (const float*)d_in[11];
    const float* bout = (const float*)d_in[12];
    float* out = (float*)d_out;

    cudaFuncSetAttribute(gemmx_kernel, cudaFuncAttributeMaxDynamicSharedMemorySize, SMEM_X);
    cudaFuncSetAttribute(step1_kernel, cudaFuncAttributeMaxDynamicSharedMemorySize, SMEM_S1);
    cudaFuncSetAttribute(step2_kernel, cudaFuncAttributeMaxDynamicSharedMemorySize, SMEM_S2);

    init_kernel<<<1024, 256>>>(b_d, x, Wmih, Wmhh, Wih, Whh, bmih, bmhh, bih, bhh);

    // hoisted input projection over all timesteps (streaming output)
    gemmx_kernel<<<dim3(N1 / 64, (T_ * B_) / 64), 256, SMEM_X>>>();

    for (int t = 0; t < T_; t++) {
        step1_kernel<<<dim3(16, 8), 384, SMEM_S1>>>(t);
        step2_kernel<<<dim3(16, 8), 512, SMEM_S2>>>(len, t);
    }

    head_kernel<<<64, 128>>>(Wout, bout, out);
}

// round 10
// speedup vs baseline: 1.0363x; 1.0363x over previous
#include <cuda_runtime.h>
#include <cuda_bf16.h>
#include <cstdint>

typedef uint32_t u32;
typedef uint64_t u64;
typedef unsigned short u16;

// ---------------------------------------------------------------------------
// MLSTMFixD round 10 (= round 9 design with the load_chunk k0 double-offset fixed):
//  - bf16 3-term split GEMMs (fp32-accurate) via mma.sync (sm_103-safe)
//  - XW = x@Wmih^T hoisted; streaming stores/loads (__stcs/__ldcs)
//  - step GEMMs: 128-thr CTAs, 32x32 warp tiles (MMA:LDSM = 3),
//    explicit fragment double-buffering, 2-stage cp.async, 3 CTAs/SM
// ---------------------------------------------------------------------------

constexpr int T_   = 128;
constexpr int B_   = 256;
constexpr int I_   = 512;
constexpr int H_   = 512;
constexpr int O_   = 5;
constexpr int KLAG = 32;
constexpr int BH   = B_ * H_;
constexpr int N1   = 3 * H_;   // 1536
constexpr int N2   = 4 * H_;   // 2048

constexpr int SMEM_X = 2 * 32768;   // gemmx: 2 stages x 32KB
constexpr int SMEM_S = 2 * 32768;   // step gemms: 2 stages x 32KB

// ------------------------- device scratch (static) -------------------------
__device__ __align__(16) u16 g_xhi[T_ * B_ * I_], g_xlo[T_ * B_ * I_];
__device__ __align__(16) u16 g_WxHi[N1 * 512],  g_WxLo[N1 * 512];    // Wmih
__device__ __align__(16) u16 g_W1Hi[N1 * 512],  g_W1Lo[N1 * 512];    // Wmhh
__device__ __align__(16) u16 g_W2Hi[N2 * 1024], g_W2Lo[N2 * 1024];   // [Wih|Whh]
__device__ __align__(16) u16 g_h1hi[BH], g_h1lo[BH];
__device__ __align__(16) u16 g_h2hi[BH], g_h2lo[BH];
__device__ float g_c2[BH];
__device__ float g_sel[BH];
__device__ float g_hist[KLAG][BH];          // circular by (t & 31)
__device__ float g_wd[KLAG][H_];
__device__ float g_XW[(size_t)T_ * B_ * N1];  // x @ Wmih^T for all t (streamed)
__device__ float g_G1[2][B_ * N1];          // K-split partials
__device__ float g_G2[2][B_ * N2];

// ------------------------------- helpers ------------------------------------
__device__ __forceinline__ u32 smem_u32(const void* p) {
    u32 a;
    asm("{ .reg .u64 t; cvta.to.shared.u64 t, %1; cvt.u32.u64 %0, t; }" : "=r"(a) : "l"(p));
    return a;
}
__device__ __forceinline__ void cpasync16(u32 dst, const void* src) {
    asm volatile("cp.async.cg.shared.global [%0], [%1], 16;" :: "r"(dst), "l"(src));
}
#define CP_COMMIT() asm volatile("cp.async.commit_group;" ::: "memory")
#define CP_WAIT0()  asm volatile("cp.async.wait_group 0;" ::: "memory")

#define LDSM4(r, addr) asm volatile(                                           \
    "ldmatrix.sync.aligned.m8n8.x4.shared.b16 {%0,%1,%2,%3}, [%4];"            \
    : "=r"((r)[0]), "=r"((r)[1]), "=r"((r)[2]), "=r"((r)[3]) : "r"(addr))

#define MMA(d, a, b0, b1) asm volatile(                                        \
    "mma.sync.aligned.m16n8k16.row.col.f32.bf16.bf16.f32 "                     \
    "{%0,%1,%2,%3}, {%4,%5,%6,%7}, {%8,%9}, {%0,%1,%2,%3};"                    \
    : "+f"((d)[0]), "+f"((d)[1]), "+f"((d)[2]), "+f"((d)[3])                   \
    : "r"((a)[0]), "r"((a)[1]), "r"((a)[2]), "r"((a)[3]), "r"(b0), "r"(b1))

__device__ __forceinline__ u16 bf16bits(__nv_bfloat16 v) {
    __nv_bfloat16_raw r = *reinterpret_cast<__nv_bfloat16_raw*>(&v);
    return r.x;
}
__device__ __forceinline__ void split1(float a, u16& h, u16& l) {
    __nv_bfloat16 bh = __float2bfloat16_rn(a);
    float r = a - __bfloat162float(bh);
    __nv_bfloat16 bl = __float2bfloat16_rn(r);
    h = bf16bits(bh);
    l = bf16bits(bl);
}
__device__ __forceinline__ void split4(float4 v, u32& h01, u32& h23, u32& l01, u32& l23) {
    u16 h0, l0, h1, l1, h2, l2, h3, l3;
    split1(v.x, h0, l0); split1(v.y, h1, l1);
    split1(v.z, h2, l2); split1(v.w, h3, l3);
    h01 = (u32)h0 | ((u32)h1 << 16);  h23 = (u32)h2 | ((u32)h3 << 16);
    l01 = (u32)l0 | ((u32)l1 << 16);  l23 = (u32)l2 | ((u32)l3 << 16);
}
__device__ __forceinline__ float sigf(float x) { return 1.0f / (1.0f + expf(-x)); }

// ------------------------------- init ---------------------------------------
__global__ __launch_bounds__(256) void init_kernel(
    const float* __restrict__ b_d,  const float* __restrict__ x,
    const float* __restrict__ Wmih, const float* __restrict__ Wmhh,
    const float* __restrict__ Wih,  const float* __restrict__ Whh)
{
    const int tid = blockIdx.x * blockDim.x + threadIdx.x;
    const int tot = gridDim.x * blockDim.x;

    const int ngx = T_ * B_ * I_ / 4;
    for (int i = tid; i < ngx; i += tot) {
        float4 v = reinterpret_cast<const float4*>(x)[i];
        u32 h01, h23, l01, l23; split4(v, h01, h23, l01, l23);
        reinterpret_cast<uint2*>(g_xhi)[i] = make_uint2(h01, h23);
        reinterpret_cast<uint2*>(g_xlo)[i] = make_uint2(l01, l23);
    }

    const int ngWx = N1 * 512 / 4;
    for (int i = tid; i < ngWx; i += tot) {
        float4 v = reinterpret_cast<const float4*>(Wmih)[i];
        u32 h01, h23, l01, l23; split4(v, h01, h23, l01, l23);
        reinterpret_cast<uint2*>(g_WxHi)[i] = make_uint2(h01, h23);
        reinterpret_cast<uint2*>(g_WxLo)[i] = make_uint2(l01, l23);
    }
    for (int i = tid; i < ngWx; i += tot) {
        float4 v = reinterpret_cast<const float4*>(Wmhh)[i];
        u32 h01, h23, l01, l23; split4(v, h01, h23, l01, l23);
        reinterpret_cast<uint2*>(g_W1Hi)[i] = make_uint2(h01, h23);
        reinterpret_cast<uint2*>(g_W1Lo)[i] = make_uint2(l01, l23);
    }
    const int ngW2 = N2 * 1024 / 4;
    for (int i = tid; i < ngW2; i += tot) {
        int e = i * 4;
        int n = e >> 10, k = e & 1023;
        const float* src = (k < 512) ? (Wih + (size_t)n * 512 + k)
                                     : (Whh + (size_t)n * 512 + (k - 512));
        float4 v = *reinterpret_cast<const float4*>(src);
        u32 h01, h23, l01, l23; split4(v, h01, h23, l01, l23);
        reinterpret_cast<uint2*>(g_W2Hi)[i] = make_uint2(h01, h23);
        reinterpret_cast<uint2*>(g_W2Lo)[i] = make_uint2(l01, l23);
    }

    float4 z4 = make_float4(0.f, 0.f, 0.f, 0.f);
    for (int i = tid; i < KLAG * BH / 4; i += tot)
        reinterpret_cast<float4*>(&g_hist[0][0])[i] = z4;
    for (int i = tid; i < BH / 4; i += tot) {
        reinterpret_cast<float4*>(g_c2)[i]  = z4;
        reinterpret_cast<float4*>(g_sel)[i] = z4;
        reinterpret_cast<uint2*>(g_h1hi)[i] = make_uint2(0u, 0u);
        reinterpret_cast<uint2*>(g_h1lo)[i] = make_uint2(0u, 0u);
        reinterpret_cast<uint2*>(g_h2hi)[i] = make_uint2(0u, 0u);
        reinterpret_cast<uint2*>(g_h2lo)[i] = make_uint2(0u, 0u);
    }

    if (tid < H_) {
        float d = 0.5f * (1.0f / (1.0f + expf(-b_d[tid])));
        float c = 1.0f;
        for (int j = 1; j <= KLAG; j++) {
            c *= ((float)(j - 1) - d) / (float)j;
            g_wd[j - 1][tid] = c;
        }
    }
}

// ------------------- XW precompute: XW = x @ Wmih^T --------------------------
// CTA 64x64, 8 warps (warp 32x16), K=512 in 8 chunks, 2-stage, streaming stores.
__global__ __launch_bounds__(256, 2) void gemmx_kernel()
{
    extern __shared__ __align__(128) char smem[];
    const u32 sb  = smem_u32(smem);
    const int tid = threadIdx.x;
    const int wid = tid >> 5, lane = tid & 31;
    const int bn  = blockIdx.x * 64;
    const int bm  = blockIdx.y * 64;

    const int lr  = tid >> 3;
    const int lcu = tid & 7;
    auto load_chunk = [&](int c, int stage) {
        const int k0 = c * 64;
        const u32 base = sb + stage * 32768;
#pragma unroll
        for (int j = 0; j < 2; j++) {
            const int r = lr + j * 32;
            const u32 so = (u32)(r * 128 + ((lcu ^ (r & 7)) << 4));
            const size_t ao = (size_t)(bm + r) * 512 + k0 + lcu * 8;
            const size_t bo = (size_t)(bn + r) * 512 + k0 + lcu * 8;
            cpasync16(base + so,         g_xhi  + ao);
            cpasync16(base + 8192 + so,  g_xlo  + ao);
            cpasync16(base + 16384 + so, g_WxHi + bo);
            cpasync16(base + 24576 + so, g_WxLo + bo);
        }
    };

    const int warp_m = wid & 1;
    const int warp_n = wid >> 1;
    const int arow   = warp_m * 32 + (lane & 15);
    const int akh    = lane >> 4;
    const int asw    = arow & 7;
    const u32 aoff0  = (u32)(arow * 128);
    const u32 aoff1  = (u32)((arow + 16) * 128);
    const int brow   = warp_n * 16 + (lane & 7) + ((lane >> 4) << 3);
    const int bkh    = (lane >> 3) & 1;
    const int bsw    = brow & 7;
    const u32 boff   = (u32)(brow * 128);

    float acc[2][2][4] = {};

    load_chunk(0, 0); CP_COMMIT();
    for (int c = 0; c < 8; c++) {
        CP_WAIT0();
        __syncthreads();
        if (c + 1 < 8) { load_chunk(c + 1, (c + 1) & 1); CP_COMMIT(); }

        const u32 Ah = sb + (c & 1) * 32768;
        const u32 Al = Ah + 8192;
        const u32 Bh = Ah + 16384;
        const u32 Bl = Ah + 24576;
#pragma unroll
        for (int kk = 0; kk < 4; kk++) {
            const u32 sa  = (((u32)(kk * 2 + akh) ^ (u32)asw) << 4);
            const u32 sbo = (((u32)(kk * 2 + bkh) ^ (u32)bsw) << 4);
            u32 ah0[4], ah1[4], al0[4], al1[4], bh[4], bl[4];
            LDSM4(ah0, Ah + aoff0 + sa);
            LDSM4(ah1, Ah + aoff1 + sa);
            LDSM4(al0, Al + aoff0 + sa);
            LDSM4(al1, Al + aoff1 + sa);
            LDSM4(bh,  Bh + boff + sbo);
            LDSM4(bl,  Bl + boff + sbo);
#pragma unroll
            for (int nt = 0; nt < 2; nt++) {
                MMA(acc[0][nt], ah0, bh[2 * nt], bh[2 * nt + 1]);
                MMA(acc[1][nt], ah1, bh[2 * nt], bh[2 * nt + 1]);
                MMA(acc[0][nt], ah0, bl[2 * nt], bl[2 * nt + 1]);
                MMA(acc[1][nt], ah1, bl[2 * nt], bl[2 * nt + 1]);
                MMA(acc[0][nt], al0, bh[2 * nt], bh[2 * nt + 1]);
                MMA(acc[1][nt], al1, bh[2 * nt], bh[2 * nt + 1]);
            }
        }
    }

#pragma unroll
    for (int mt = 0; mt < 2; mt++)
#pragma unroll
        for (int nt = 0; nt < 2; nt++) {
            const int gm = bm + warp_m * 32 + mt * 16 + (lane >> 2);
            const int gn = bn + warp_n * 16 + nt * 8 + 2 * (lane & 3);
            __stcs(reinterpret_cast<float2*>(&g_XW[(size_t)gm * N1 + gn]),
                   make_float2(acc[mt][nt][0], acc[mt][nt][1]));
            __stcs(reinterpret_cast<float2*>(&g_XW[(size_t)(gm + 8) * N1 + gn]),
                   make_float2(acc[mt][nt][2], acc[mt][nt][3]));
        }
}

// ----------------------- step GEMMs (high-ILP rebuild) -----------------------
// SET=1: G1[kz][256,1536] = h1 @ Wmhh^T      grid (24, 4, 2)  K=256/CTA, 4 chunks
// SET=2: G2[kz][256,2048] = [h1n|h2] @ W2^T  grid (32, 4, 2)  K=512/CTA, 8 chunks
// CTA 64x64, 128 thr (4 warps 2x2, warp tile 32x32 -> 8 LDSM : 24 MMA per k16),
// fragment double-buffering across k16 sub-steps, 2-stage cp.async, 3 CTAs/SM.
template <int SET>
__global__ __launch_bounds__(128, 3) void gemm_kernel(int t)
{
    constexpr int NC  = (SET == 1) ? 4 : 8;
    constexpr int ldB = (SET == 2) ? 1024 : 512;
    constexpr int ldG = (SET == 2) ? N2 : N1;

    extern __shared__ __align__(128) char smem[];
    const u32 sb  = smem_u32(smem);
    const int tid = threadIdx.x;
    const int wid = tid >> 5, lane = tid & 31;
    const int bn  = blockIdx.x * 64;
    const int bm  = blockIdx.y * 64;
    const int kz  = blockIdx.z;
    const int kbase = (SET == 1) ? kz * 256 : kz * 512;

    const u16* __restrict__ BHi = (SET == 1) ? g_W1Hi : g_W2Hi;
    const u16* __restrict__ BLo = (SET == 1) ? g_W1Lo : g_W2Lo;
    float* __restrict__ G = (SET == 1) ? g_G1[kz] : g_G2[kz];

    // loader: 2048 16B units per chunk, 16 per thread (4 per 8KB tile)
    const int lr  = tid >> 3;          // 0..15
    const int lcu = tid & 7;
    auto load_chunk = [&](int c, int stage) {
        const int k0 = kbase + c * 64;
        const u16* ah; const u16* al; int kloc;
        if (SET == 2 && k0 >= 512) { ah = g_h2hi; al = g_h2lo; kloc = k0 - 512; }
        else                       { ah = g_h1hi; al = g_h1lo; kloc = k0;       }
        const u32 base = sb + stage * 32768;
#pragma unroll
        for (int j = 0; j < 4; j++) {
            const int r = lr + j * 16;                 // 0..63
            const u32 so = (u32)(r * 128 + ((lcu ^ (r & 7)) << 4));
            const size_t ao = (size_t)(bm + r) * 512 + kloc + lcu * 8;
            const size_t bo = (size_t)(bn + r) * ldB + k0 + lcu * 8;
            cpasync16(base + so,         ah  + ao);
            cpasync16(base + 8192 + so,  al  + ao);
            cpasync16(base + 16384 + so, BHi + bo);
            cpasync16(base + 24576 + so, BLo + bo);
        }
    };

    // fragment addressing: warp tile 32x32
    const int warp_m = wid & 1;
    const int warp_n = wid >> 1;
    const int arow   = warp_m * 32 + (lane & 15);
    const int akh    = lane >> 4;
    const int asw    = arow & 7;
    const u32 aoff0  = (u32)(arow * 128);
    const u32 aoff1  = (u32)((arow + 16) * 128);
    const int brow   = warp_n * 32 + (lane & 7) + ((lane >> 4) << 3);
    const int bkh    = (lane >> 3) & 1;
    const int bsw    = brow & 7;                 // (brow+16)&7 == bsw
    const u32 boff0  = (u32)(brow * 128);
    const u32 boff1  = (u32)((brow + 16) * 128);

    float acc[2][4][4] = {};
    u32 fr[2][8][4];    // double-buffered fragments: [buf][ah0 ah1 al0 al1 bh0 bh1 bl0 bl1]

    u32 Ah = 0, Al = 0, Bh = 0, Bl = 0;
    auto load_frags = [&](int kk, int fb) {
        const u32 sa  = (((u32)(kk * 2 + akh) ^ (u32)asw) << 4);
        const u32 sbo = (((u32)(kk * 2 + bkh) ^ (u32)bsw) << 4);
        LDSM4(fr[fb][0], Ah + aoff0 + sa);
        LDSM4(fr[fb][1], Ah + aoff1 + sa);
        LDSM4(fr[fb][2], Al + aoff0 + sa);
        LDSM4(fr[fb][3], Al + aoff1 + sa);
        LDSM4(fr[fb][4], Bh + boff0 + sbo);
        LDSM4(fr[fb][5], Bh + boff1 + sbo);
        LDSM4(fr[fb][6], Bl + boff0 + sbo);
        LDSM4(fr[fb][7], Bl + boff1 + sbo);
    };
    auto do_mmas = [&](int fb) {
#pragma unroll
        for (int i = 0; i < 2; i++) {        // m-frag (ah0/ah1)
            u32* ah = fr[fb][i];
            u32* al = fr[fb][2 + i];
#pragma unroll
            for (int g = 0; g < 2; g++) {    // B 16-col group
                u32* bh = fr[fb][4 + g];
                u32* bl = fr[fb][6 + g];
#pragma unroll
                for (int n8 = 0; n8 < 2; n8++) {
                    float* d = acc[i][g * 2 + n8];
                    MMA(d, ah, bh[2 * n8], bh[2 * n8 + 1]);
                    MMA(d, ah, bl[2 * n8], bl[2 * n8 + 1]);
                    MMA(d, al, bh[2 * n8], bh[2 * n8 + 1]);
                }
            }
        }
    };

    load_chunk(0, 0); CP_COMMIT();

    for (int c = 0; c < NC; c++) {
        CP_WAIT0();
        __syncthreads();
        if (c + 1 < NC) { load_chunk(c + 1, (c + 1) & 1); CP_COMMIT(); }

        Ah = sb + (c & 1) * 32768;
        Al = Ah + 8192;
        Bh = Ah + 16384;
        Bl = Ah + 24576;

        load_frags(0, 0);
#pragma unroll
        for (int kk = 0; kk < 4; kk++) {
            if (kk < 3) load_frags(kk + 1, (kk + 1) & 1);
            do_mmas(kk & 1);
        }
    }

    // epilogue: fp32 accumulators -> G partials
#pragma unroll
    for (int i = 0; i < 2; i++)
#pragma unroll
        for (int j = 0; j < 4; j++) {
            const int gm = bm + warp_m * 32 + i * 16 + (lane >> 2);
            const int gn = bn + warp_n * 32 + j * 8 + 2 * (lane & 3);
            *reinterpret_cast<float2*>(&G[(size_t)gm * ldG + gn]) =
                make_float2(acc[i][j][0], acc[i][j][1]);
            *reinterpret_cast<float2*>(&G[(size_t)(gm + 8) * ldG + gn]) =
                make_float2(acc[i][j][2], acc[i][j][3]);
        }
}

// --------------------- epilogue 1: mLSTM gates + frac filter -----------------
__global__ __launch_bounds__(256) void epi1_kernel(
    const float* __restrict__ bmih, const float* __restrict__ bmhh, int t)
{
    const int idx = blockIdx.x * blockDim.x + threadIdx.x;
    const int b = idx >> 9, hc = idx & 511;
    const float* __restrict__ Ga = g_G1[0] + (size_t)b * N1;
    const float* __restrict__ Gb = g_G1[1] + (size_t)b * N1;
    const float* __restrict__ Gx = g_XW + ((size_t)t * B_ + b) * N1;

    float vi = sigf (Ga[hc]        + Gb[hc]        + __ldcs(Gx + hc)        + bmih[hc]        + bmhh[hc]);
    float vo = sigf (Ga[512 + hc]  + Gb[512 + hc]  + __ldcs(Gx + 512 + hc)  + bmih[512 + hc]  + bmhh[512 + hc]);
    float vg = tanhf(Ga[1024 + hc] + Gb[1024 + hc] + __ldcs(Gx + 1024 + hc) + bmih[1024 + hc] + bmhh[1024 + hc]);

    float fs = 0.0f;
#pragma unroll
    for (int j = 1; j <= KLAG; j++)
        fs = fmaf(g_wd[j - 1][hc], g_hist[(t - j) & (KLAG - 1)][idx], fs);

    float c1 = vi * vg - fs;
    g_hist[t & (KLAG - 1)][idx] = c1;
    float h1n = vo * tanhf(c1);
    split1(h1n, g_h1hi[idx], g_h1lo[idx]);
}

// --------------------- epilogue 2: LSTM cell + gather ------------------------
__global__ __launch_bounds__(256) void epi2_kernel(
    const float* __restrict__ bih, const float* __restrict__ bhh,
    const int* __restrict__ length, int t)
{
    const int idx = blockIdx.x * blockDim.x + threadIdx.x;
    const int b = idx >> 9, hc = idx & 511;
    const float* __restrict__ Ga = g_G2[0] + (size_t)b * N2;
    const float* __restrict__ Gb = g_G2[1] + (size_t)b * N2;

    float xi = sigf (Ga[hc]        + Gb[hc]        + bih[hc]        + bhh[hc]);
    float xf = sigf (Ga[512 + hc]  + Gb[512 + hc]  + bih[512 + hc]  + bhh[512 + hc]);
    float xg = tanhf(Ga[1024 + hc] + Gb[1024 + hc] + bih[1024 + hc] + bhh[1024 + hc]);
    float xo = sigf (Ga[1536 + hc] + Gb[1536 + hc] + bih[1536 + hc] + bhh[1536 + hc]);

    float cn = xf * g_c2[idx] + xi * xg;
    g_c2[idx] = cn;
    float hv = tanhf(xo * tanhf(cn));
    split1(hv, g_h2hi[idx], g_h2lo[idx]);
    if (length[b] == t) g_sel[idx] = hv;
}

// ------------------------------- head ---------------------------------------
__global__ __launch_bounds__(128) void head_kernel(
    const float* __restrict__ Wout, const float* __restrict__ bout,
    float* __restrict__ out)
{
    const int warp = (blockIdx.x * blockDim.x + threadIdx.x) >> 5;
    const int lane = threadIdx.x & 31;
    if (warp >= B_) return;

    float p[O_] = {0.f, 0.f, 0.f, 0.f, 0.f};
    for (int h = lane; h < H_; h += 32) {
        float s = g_sel[warp * H_ + h];
#pragma unroll
        for (int o = 0; o < O_; o++) p[o] = fmaf(s, Wout[o * H_ + h], p[o]);
    }
#pragma unroll
    for (int o = 0; o < O_; o++)
#pragma unroll
        for (int off = 16; off > 0; off >>= 1)
            p[o] += __shfl_xor_sync(0xffffffffu, p[o], off);

    if (lane == 0) {
        float l[O_], m = -1e30f;
#pragma unroll
        for (int o = 0; o < O_; o++) { l[o] = p[o] + bout[o]; m = fmaxf(m, l[o]); }
        float s = 0.0f;
#pragma unroll
        for (int o = 0; o < O_; o++) s += expf(l[o] - m);
        float ls = logf(s);
#pragma unroll
        for (int o = 0; o < O_; o++) out[warp * O_ + o] = l[o] - m - ls;
    }
}

// ----------------------------- launcher -------------------------------------
extern "C" void kernel_launch(void* const* d_in, const int* in_sizes, int n_in,
                              void* d_out, int out_size)
{
    const float* x    = (const float*)d_in[0];
    const int*   len  = (const int*)  d_in[1];
    const float* b_d  = (const float*)d_in[2];
    const float* Wmih = (const float*)d_in[3];
    const float* Wmhh = (const float*)d_in[4];
    const float* bmih = (const float*)d_in[5];
    const float* bmhh = (const float*)d_in[6];
    const float* Wih  = (const float*)d_in[7];
    const float* Whh  = (const float*)d_in[8];
    const float* bih  = (const float*)d_in[9];
    const float* bhh  = (const float*)d_in[10];
    const float* Wout = (const float*)d_in[11];
    const float* bout = (const float*)d_in[12];
    float* out = (float*)d_out;

    cudaFuncSetAttribute(gemmx_kernel,   cudaFuncAttributeMaxDynamicSharedMemorySize, SMEM_X);
    cudaFuncSetAttribute(gemm_kernel<1>, cudaFuncAttributeMaxDynamicSharedMemorySize, SMEM_S);
    cudaFuncSetAttribute(gemm_kernel<2>, cudaFuncAttributeMaxDynamicSharedMemorySize, SMEM_S);

    init_kernel<<<1024, 256>>>(b_d, x, Wmih, Wmhh, Wih, Whh);

    // hoisted input projection over all timesteps (streaming output)
    gemmx_kernel<<<dim3(N1 / 64, (T_ * B_) / 64), 256, SMEM_X>>>();

    for (int t = 0; t < T_; t++) {
        gemm_kernel<1><<<dim3(N1 / 64, 4, 2), 128, SMEM_S>>>(t);
        epi1_kernel<<<BH / 256, 256>>>(bmih, bmhh, t);
        gemm_kernel<2><<<dim3(N2 / 64, 4, 2), 128, SMEM_S>>>(t);
        epi2_kernel<<<BH / 256, 256>>>(bih, bhh, len, t);
    }

    head_kernel<<<64, 128>>>(Wout, bout, out);
}